// round 3
// baseline (speedup 1.0000x reference)
#include <cuda_runtime.h>
#include <cstdint>

// QuantLinear 4-bit matvec, GB300 (sm_103a) — single-kernel, 512-CTA version
//   y[o] = bias[o] + scales[o] * sum_k x[k]*w[k,o] - zeros[o] * sum_k x[k]
//   w[r*8+j, o] = (qweight[r,o] >> 4j) & 0xF
//
// R1: 128 CTAs -> latency-starved (DRAM 32%). R2: split-K two-launch; main
// kernel hit ~5.2us but the epilogue launch cost 5.8us. R3: one launch,
// 512 CTAs x 256 thr, 16 outputs/CTA over full K; fused epilogue.
// x quantized to int16 (scale 6553), nibbles as packed u8 via 2 LOP3 masks,
// 4x dp2a per word (integer-exact, deterministic).

#define K_IN   8192
#define N_OUT  8192
#define RW     1024          // qweight rows
#define XSF    6553.0f

__device__ __forceinline__ int dp2a_lo(int a, unsigned b, int c) {
    int d;
    asm("dp2a.lo.s32.u32 %0, %1, %2, %3;" : "=r"(d) : "r"(a), "r"(b), "r"(c));
    return d;
}
__device__ __forceinline__ int dp2a_hi(int a, unsigned b, int c) {
    int d;
    asm("dp2a.hi.s32.u32 %0, %1, %2, %3;" : "=r"(d) : "r"(a), "r"(b), "r"(c));
    return d;
}

__global__ __launch_bounds__(256, 4)
void qlin4_kernel(const float* __restrict__ x,
                  const uint4* __restrict__ qw,     // [RW, N_OUT/4]
                  const float* __restrict__ scales,
                  const float* __restrict__ zeros,
                  const float* __restrict__ bias,
                  float* __restrict__ out)
{
    // Packed int16 x in TRANSPOSED layout sxq[rr*64 + ks] for group
    // g = ks*16 + rr  ->  phase-2 LDS.128 lanes hit consecutive 16B
    // addresses (conflict-free). dp2a byte-lane order per group:
    // { (x0|x2), (x4|x6), (x1|x3), (x5|x7) }
    __shared__ int4 sxq[RW];          // 16 KB
    __shared__ int4 sredA[64 * 4];    //  4 KB: [kslice][oq] int partials
    __shared__ int  redsum[256];      //  1 KB

    const int tid = threadIdx.x;

    // ---- Phase 1: quantize + pack x; integer xsum ----
    int s16 = 0;
#pragma unroll
    for (int i = 0; i < 4; i++) {
        const int g = i * 256 + tid;                // 8-value group = qweight row g
        float4 a = __ldg((const float4*)x + 2 * g);
        float4 b = __ldg((const float4*)x + 2 * g + 1);
        int q0 = __float2int_rn(a.x * XSF);
        int q1 = __float2int_rn(a.y * XSF);
        int q2 = __float2int_rn(a.z * XSF);
        int q3 = __float2int_rn(a.w * XSF);
        int q4 = __float2int_rn(b.x * XSF);
        int q5 = __float2int_rn(b.y * XSF);
        int q6 = __float2int_rn(b.z * XSF);
        int q7 = __float2int_rn(b.w * XSF);
        int4 p;
        p.x = (q0 & 0xFFFF) | (q2 << 16);   // even nibbles 0,2 (lo bytes 0,1)
        p.y = (q4 & 0xFFFF) | (q6 << 16);   // even nibbles 4,6 (lo bytes 2,3)
        p.z = (q1 & 0xFFFF) | (q3 << 16);   // odd  nibbles 1,3 (hi bytes 0,1)
        p.w = (q5 & 0xFFFF) | (q7 << 16);   // odd  nibbles 5,7 (hi bytes 2,3)
        const int rr = g & 15;
        const int ks = g >> 4;
        sxq[rr * 64 + ks] = p;              // transposed store
        s16 += q0 + q1 + q2 + q3 + q4 + q5 + q6 + q7;
    }
    redsum[tid] = s16;
    __syncthreads();
#pragma unroll
    for (int off = 128; off > 0; off >>= 1) {
        if (tid < off) redsum[tid] += redsum[tid + off];
        __syncthreads();
    }
    const int xsumi = redsum[0];   // into register before redsum is reused
    __syncthreads();

    // ---- Phase 2: stream qweight; 16 outputs/CTA, 64 K-slices ----
    const int oq  = tid & 3;                       // uint4 column within CTA
    const int ks  = tid >> 2;                      // K slice (16 rows each)
    const int col = blockIdx.x * 4 + oq;
    const uint4* p = qw + (size_t)(ks * 16) * (N_OUT / 4) + col;

    int a0 = 0, a1 = 0, a2 = 0, a3 = 0;
#pragma unroll 8
    for (int rr = 0; rr < 16; rr++) {
        uint4 q = __ldg(p);
        p += N_OUT / 4;
        int4 xp = sxq[rr * 64 + ks];               // conflict-free LDS.128

        unsigned lo, hi;
        lo = q.x & 0x0F0F0F0Fu; hi = (q.x >> 4) & 0x0F0F0F0Fu;
        a0 = dp2a_lo(xp.x, lo, a0); a0 = dp2a_hi(xp.y, lo, a0);
        a0 = dp2a_lo(xp.z, hi, a0); a0 = dp2a_hi(xp.w, hi, a0);

        lo = q.y & 0x0F0F0F0Fu; hi = (q.y >> 4) & 0x0F0F0F0Fu;
        a1 = dp2a_lo(xp.x, lo, a1); a1 = dp2a_hi(xp.y, lo, a1);
        a1 = dp2a_lo(xp.z, hi, a1); a1 = dp2a_hi(xp.w, hi, a1);

        lo = q.z & 0x0F0F0F0Fu; hi = (q.z >> 4) & 0x0F0F0F0Fu;
        a2 = dp2a_lo(xp.x, lo, a2); a2 = dp2a_hi(xp.y, lo, a2);
        a2 = dp2a_lo(xp.z, hi, a2); a2 = dp2a_hi(xp.w, hi, a2);

        lo = q.w & 0x0F0F0F0Fu; hi = (q.w >> 4) & 0x0F0F0F0Fu;
        a3 = dp2a_lo(xp.x, lo, a3); a3 = dp2a_hi(xp.y, lo, a3);
        a3 = dp2a_lo(xp.z, hi, a3); a3 = dp2a_hi(xp.w, hi, a3);
    }
    sredA[ks * 4 + oq] = make_int4(a0, a1, a2, a3);
    __syncthreads();

    // ---- Phase 3: two-stage reduce over 64 K-slices + fused epilogue ----
    // View sredA as int[64][16]: [kslice][local output].
    {
        const int* sr = (const int*)sredA;
        const int og = tid & 15;                   // local output
        const int sg = tid >> 4;                   // slice group (4 slices)
        int s = 0;
#pragma unroll
        for (int j = 0; j < 4; j++) s += sr[(sg * 4 + j) * 16 + og];
        redsum[sg * 16 + og] = s;                  // redsum reused: [16][16]
    }
    __syncthreads();

    if (tid < 16) {
        int s = 0;
#pragma unroll
        for (int g2 = 0; g2 < 16; g2++) s += redsum[g2 * 16 + tid];
        const int o = blockIdx.x * 16 + tid;
        const float inv = 1.0f / XSF;
        float xw   = (float)s * inv;
        float xsum = (float)xsumi * inv;
        out[o] = __ldg(bias + o) + __ldg(scales + o) * xw - __ldg(zeros + o) * xsum;
    }
}

extern "C" void kernel_launch(void* const* d_in, const int* in_sizes, int n_in,
                              void* d_out, int out_size)
{
    // metadata order: x, qweight, scales, zeros, bias
    const float* x      = (const float*)d_in[0];
    const uint4* qw     = (const uint4*)d_in[1];
    const float* scales = (const float*)d_in[2];
    const float* zeros  = (const float*)d_in[3];
    const float* bias   = (const float*)d_in[4];
    float* out          = (float*)d_out;

    qlin4_kernel<<<N_OUT / 16, 256>>>(x, qw, scales, zeros, bias, out);
}